// round 7
// baseline (speedup 1.0000x reference)
#include <cuda_runtime.h>
#include <cuda_bf16.h>
#include <cstdint>

#define NG 32
#define SV_P 65
#define RED_P 18

// A fragments hi/lo interleaved: [c(8)][mt(1024)][kt(16)][lane(32)] x {hi,lo} uint4
__device__ uint4 g_Af[8 * 1024 * 16 * 32 * 2];
// B fragments hi/lo interleaved: [g(32)][kt(16)][nt(32)][lane(32)] uint4 {h0,h1,l0,l1}
__device__ uint4 g_Bf[NG * 16 * 32 * 32];

// ---- smem map (bytes) ----
#define OFF_BIAS 0          // 1024
#define OFF_SV   1024       // 128*65*4 = 33280
#define OFF_RED  34304      // 4*128*18*4 = 36864 (also v0's sTe scratch)
#define OFF_SA   71168      // 2 x 32768
#define OFF_SB   136704     // 2 x 32768
#define SMEM_SZ  202240

__device__ __forceinline__ uint32_t s2u(const void* p) {
    uint32_t a;
    asm("{ .reg .u64 t; cvta.to.shared.u64 t, %1; cvt.u32.u64 %0, t; }" : "=r"(a) : "l"(p));
    return a;
}
__device__ __forceinline__ uint32_t pack_hi(float x, float y) {
    __nv_bfloat162 h = __halves2bfloat162(__float2bfloat16(x), __float2bfloat16(y));
    return *(uint32_t*)&h;
}
__device__ __forceinline__ uint32_t pack_lo(float x, float y, uint32_t hb) {
    __nv_bfloat162 h = *(__nv_bfloat162*)&hb;
    __nv_bfloat162 lo = __halves2bfloat162(
        __float2bfloat16(x - __bfloat162float(h.x)),
        __float2bfloat16(y - __bfloat162float(h.y)));
    return *(uint32_t*)&lo;
}
__device__ __forceinline__ void mma_bf16(float* c, const uint32_t* a, uint32_t b0, uint32_t b1) {
    asm volatile(
        "mma.sync.aligned.m16n8k16.row.col.f32.bf16.bf16.f32 "
        "{%0,%1,%2,%3}, {%4,%5,%6,%7}, {%8,%9}, {%0,%1,%2,%3};"
        : "+f"(c[0]), "+f"(c[1]), "+f"(c[2]), "+f"(c[3])
        : "r"(a[0]), "r"(a[1]), "r"(a[2]), "r"(a[3]), "r"(b0), "r"(b1));
}
__device__ __forceinline__ void cpa16(uint32_t dst, const void* src) {
    asm volatile("cp.async.cg.shared.global [%0], [%1], 16;" :: "r"(dst), "l"(src) : "memory");
}
#define CP_COMMIT() asm volatile("cp.async.commit_group;" ::: "memory")
#define CP_WAIT0()  asm volatile("cp.async.wait_group 0;" ::: "memory")

// ---------------- prep_A: nh f32 -> A fragments hi/lo interleaved ----------------
__global__ __launch_bounds__(256) void prep_A(const float* __restrict__ nh) {
    const int blk = blockIdx.x;              // 8192 = c(8) x mt(1024)
    const int c = blk >> 10, mt = blk & 1023;
    #pragma unroll
    for (int s = 0; s < 2; s++) {
        int u = threadIdx.x + s * 256;       // kt(16) x lane(32)
        int kt = u >> 5, l = u & 31;
        int row = mt * 16 + (l >> 2);
        int k = kt * 16 + (l & 3) * 2;
        const float* p = nh + ((size_t)row * 8 + c) * 256 + k;
        float2 x0 = __ldg((const float2*)p);
        float2 x1 = __ldg((const float2*)(p + 8 * 2048));
        float2 x2 = __ldg((const float2*)(p + 8));
        float2 x3 = __ldg((const float2*)(p + 8 * 2048 + 8));
        uint32_t h0 = pack_hi(x0.x, x0.y), h1 = pack_hi(x1.x, x1.y);
        uint32_t h2 = pack_hi(x2.x, x2.y), h3 = pack_hi(x3.x, x3.y);
        size_t o = ((size_t)(c * 1024 + mt) * 16 + kt) * 32 + l;
        g_Af[2 * o]     = make_uint4(h0, h1, h2, h3);
        g_Af[2 * o + 1] = make_uint4(pack_lo(x0.x, x0.y, h0), pack_lo(x1.x, x1.y, h1),
                                     pack_lo(x2.x, x2.y, h2), pack_lo(x3.x, x3.y, h3));
    }
}

// ---------------- prep_B: U f32 -> B fragments hi/lo interleaved ----------------
__global__ __launch_bounds__(256) void prep_B(const float* __restrict__ U) {
    const int blk = blockIdx.x;              // 512 = g(32) x kt(16)
    const int g = blk >> 4, kt = blk & 15;
    const float* Ug = U + (size_t)g * 256 * 272;
    #pragma unroll
    for (int s = 0; s < 4; s++) {
        int u = threadIdx.x + s * 256;       // nt(32) x lane(32)
        int nt = u >> 5, l = u & 31;
        int k0 = kt * 16 + (l & 3) * 2, n0 = nt * 8 + (l >> 2);
        float u0 = __ldg(Ug + (size_t)k0 * 272 + n0);
        float u1 = __ldg(Ug + (size_t)(k0 + 1) * 272 + n0);
        float u8 = __ldg(Ug + (size_t)(k0 + 8) * 272 + n0);
        float u9 = __ldg(Ug + (size_t)(k0 + 9) * 272 + n0);
        uint32_t h0 = pack_hi(u0, u1), h1 = pack_hi(u8, u9);
        uint32_t l0 = pack_lo(u0, u1, h0), l1 = pack_lo(u8, u9, h1);
        g_Bf[((size_t)(g * 16 + kt) * 32 + nt) * 32 + l] = make_uint4(h0, h1, l0, l1);
    }
}

// ---------------- main fused kernel: 256 threads, 8 warps (mw 2 x nwp 4, tile 64x32) ----
__global__ __launch_bounds__(256, 1)
void tt_main(const float* __restrict__ te, const float* __restrict__ bB,
             const float* __restrict__ Ut, const float* __restrict__ bt,
             const float* __restrict__ Uo, const float* __restrict__ bo,
             float* __restrict__ out)
{
    extern __shared__ __align__(16) char smem[];
    const uint32_t sbase = s2u(smem);
    float* sBias = (float*)(smem + OFF_BIAS);
    float* sV    = (float*)(smem + OFF_SV);
    float* red   = (float*)(smem + OFF_RED);

    const int tid = threadIdx.x;
    const int l   = tid & 31, w = tid >> 5;
    const int mw  = w >> 2,  nwp = w & 3;       // warp grid 2M x 4N
    const int b0  = blockIdx.x * 128;
    const int mt0 = blockIdx.x * 8;

    // ================= v0 = te @ U_type + b_type =================
    {
        float* sUt = (float*)(smem + OFF_SA);   // 4096 floats
        float* sTe = red;                       // 128x64, float4-rotated (32 KB <= red)
        #pragma unroll
        for (int i = 0; i < 4; i++) {
            int idx = tid + i * 256;
            ((float4*)sUt)[idx] = __ldg((const float4*)Ut + idx);
        }
        #pragma unroll
        for (int i = 0; i < 8; i++) {
            int u = tid + i * 256;              // 2048 float4 units
            int m = u >> 4, t4 = u & 15;
            *(float4*)(sTe + m * 64 + ((t4 + m) & 15) * 4) =
                __ldg((const float4*)(te + (size_t)(b0 + m) * 64) + t4);
        }
        __syncthreads();
        const int m = tid & 127;
        #pragma unroll 1
        for (int half = 0; half < 2; half++) {
            const int aa = (tid >> 7) + 2 * half;
            float4 q0 = __ldg((const float4*)(bt + aa * 16) + 0);
            float4 q1 = __ldg((const float4*)(bt + aa * 16) + 1);
            float4 q2 = __ldg((const float4*)(bt + aa * 16) + 2);
            float4 q3 = __ldg((const float4*)(bt + aa * 16) + 3);
            float vv[16] = {q0.x,q0.y,q0.z,q0.w, q1.x,q1.y,q1.z,q1.w,
                            q2.x,q2.y,q2.z,q2.w, q3.x,q3.y,q3.z,q3.w};
            #pragma unroll 4
            for (int t4 = 0; t4 < 16; t4++) {
                float4 xv = *(float4*)(sTe + m * 64 + ((t4 + m) & 15) * 4);
                float xs[4] = {xv.x, xv.y, xv.z, xv.w};
                #pragma unroll
                for (int e = 0; e < 4; e++) {
                    float x = xs[e];
                    const float4* ur = (const float4*)(sUt + aa * 1024 + (t4 * 4 + e) * 16);
                    float4 u0 = ur[0], u1 = ur[1], u2 = ur[2], u3 = ur[3];
                    vv[0]+=x*u0.x; vv[1]+=x*u0.y; vv[2]+=x*u0.z; vv[3]+=x*u0.w;
                    vv[4]+=x*u1.x; vv[5]+=x*u1.y; vv[6]+=x*u1.z; vv[7]+=x*u1.w;
                    vv[8]+=x*u2.x; vv[9]+=x*u2.y; vv[10]+=x*u2.z; vv[11]+=x*u2.w;
                    vv[12]+=x*u3.x; vv[13]+=x*u3.y; vv[14]+=x*u3.z; vv[15]+=x*u3.w;
                }
            }
            #pragma unroll
            for (int j = 0; j < 16; j++) sV[m * SV_P + aa * 16 + j] = vv[j];
        }
        __syncthreads();
    }

    // ================= pipeline =================
    auto issue = [&](int q) {
        const int g = q >> 3, npass = (q >> 2) & 1, kc = q & 3, buf = q & 1;
        const int c = g >> 2;
        const uint32_t aDst = sbase + OFF_SA + buf * 32768;
        #pragma unroll
        for (int s = 0; s < 4; s++) {
            int u = tid + s * 256;              // 1024: mtL(8) x ktL(4) x l(32)
            int mtL = u >> 7, ktL = (u >> 5) & 3, ll = u & 31;
            size_t o = ((size_t)(c * 1024 + mt0 + mtL) * 16 + kc * 4 + ktL) * 32 + ll;
            cpa16(aDst + u * 16,         g_Af + 2 * o);
            cpa16(aDst + 16384 + u * 16, g_Af + 2 * o + 1);
        }
        const uint32_t bDst = sbase + OFF_SB + buf * 32768;
        #pragma unroll
        for (int s = 0; s < 8; s++) {
            int u = tid + s * 256;              // 2048: ktL(4) x ntL(16) x l(32)
            int ktL = u >> 9, ntL = (u >> 5) & 15, ll = u & 31;
            size_t o = ((size_t)(g * 16 + kc * 4 + ktL) * 32 + npass * 16 + ntL) * 32 + ll;
            cpa16(bDst + u * 16, g_Bf + o);
        }
        CP_COMMIT();
    };

    float nvp2[2][4];
    #pragma unroll
    for (int it = 0; it < 2; it++)
        #pragma unroll
        for (int e = 0; e < 4; e++) nvp2[it][e] = 0.f;

    auto reduce_half = [&](int aP, int doStore) {
        #pragma unroll
        for (int it = 0; it < 2; it++) {
            int t = tid + it * 256, row = t & 127, jq = t >> 7;
            #pragma unroll
            for (int e = 0; e < 4; e++) {
                float s = red[(0 * 128 + row) * RED_P + jq * 4 + e]
                        + red[(1 * 128 + row) * RED_P + jq * 4 + e]
                        + red[(2 * 128 + row) * RED_P + jq * 4 + e]
                        + red[(3 * 128 + row) * RED_P + jq * 4 + e];
                nvp2[it][e] += s;
                if (doStore) {
                    sV[row * SV_P + aP * 16 + jq * 4 + e] = nvp2[it][e];
                    nvp2[it][e] = 0.f;
                }
            }
        }
    };

    issue(0);

    float acc[4][4][4];   // mt x nt x frag

    #pragma unroll 1
    for (int q = 0; q < 256; q++) {
        const int g = q >> 3, npass = (q >> 2) & 1, kc = q & 3, buf = q & 1;
        const int a = g & 3;

        CP_WAIT0();
        __syncthreads();
        if (q + 1 < 256) issue(q + 1);

        if ((q & 7) == 4)            reduce_half(0, 0);
        else if ((q & 7) == 0 && q)  reduce_half((g - 1) & 3, 1);

        if (kc == 0 && npass == 0 && tid < 64)
            ((float4*)sBias)[tid] = __ldg((const float4*)(bB + (size_t)g * 272) + tid);
        if (kc == 0) {
            #pragma unroll
            for (int mt = 0; mt < 4; mt++)
                #pragma unroll
                for (int nt = 0; nt < 4; nt++)
                    #pragma unroll
                    for (int e = 0; e < 4; e++) acc[mt][nt][e] = 0.f;
        }

        // ---- compute 4 k-tiles ----
        const char* sAb = smem + OFF_SA + buf * 32768;
        const char* sBb = smem + OFF_SB + buf * 32768;
        #pragma unroll
        for (int ktL = 0; ktL < 4; ktL++) {
            uint32_t Ah[4][4], Al[4][4];
            #pragma unroll
            for (int mt = 0; mt < 4; mt++) {
                int mtL = mw * 4 + mt;
                *(uint4*)Ah[mt] = *(const uint4*)(sAb + ((mtL * 4 + ktL) * 32 + l) * 16);
                *(uint4*)Al[mt] = *(const uint4*)(sAb + 16384 + ((mtL * 4 + ktL) * 32 + l) * 16);
            }
            uint4 Bq[4];
            #pragma unroll
            for (int nt = 0; nt < 4; nt++)
                Bq[nt] = *(const uint4*)(sBb + ((ktL * 16 + nwp * 4 + nt) * 32 + l) * 16);
            #pragma unroll
            for (int nt = 0; nt < 4; nt++)
                #pragma unroll
                for (int mt = 0; mt < 4; mt++)
                    mma_bf16(acc[mt][nt], Ah[mt], Bq[nt].x, Bq[nt].y);
            #pragma unroll
            for (int nt = 0; nt < 4; nt++)
                #pragma unroll
                for (int mt = 0; mt < 4; mt++)
                    mma_bf16(acc[mt][nt], Ah[mt], Bq[nt].z, Bq[nt].w);
            #pragma unroll
            for (int nt = 0; nt < 4; nt++)
                #pragma unroll
                for (int mt = 0; mt < 4; mt++)
                    mma_bf16(acc[mt][nt], Al[mt], Bq[nt].x, Bq[nt].y);
        }

        // ---- epilogue: write scan partials (no sync; reduction deferred) ----
        if (kc == 3) {
            const int i0 = npass * 8 + nwp * 2, i1 = i0 + 1;
            const int j0 = (l & 3) * 2;
            float2 b00 = *(float2*)(sBias + i0 * 16 + j0);
            float2 b01 = *(float2*)(sBias + i1 * 16 + j0);
            float2 b10 = *(float2*)(sBias + i0 * 16 + j0 + 8);
            float2 b11 = *(float2*)(sBias + i1 * 16 + j0 + 8);
            const float add1 = (i1 == 15) ? 1.f : 0.f;
            const int rbase = mw * 64 + (l >> 2);
            #pragma unroll
            for (int p = 0; p < 8; p++) {
                int row = rbase + p * 8;
                int mt = p >> 1, h = (p & 1) * 2;
                float c0 = sV[row * SV_P + a * 16 + i0];
                float c1 = sV[row * SV_P + a * 16 + i1] + add1;
                float2 pj, pk;
                pj.x = c0 * (acc[mt][0][h+0] + b00.x) + c1 * (acc[mt][2][h+0] + b01.x);
                pj.y = c0 * (acc[mt][0][h+1] + b00.y) + c1 * (acc[mt][2][h+1] + b01.y);
                pk.x = c0 * (acc[mt][1][h+0] + b10.x) + c1 * (acc[mt][3][h+0] + b11.x);
                pk.y = c0 * (acc[mt][1][h+1] + b10.y) + c1 * (acc[mt][3][h+1] + b11.y);
                *(float2*)(red + (nwp * 128 + row) * RED_P + j0)     = pj;
                *(float2*)(red + (nwp * 128 + row) * RED_P + j0 + 8) = pk;
            }
        }
    }

    __syncthreads();                // final epilogue partials visible
    reduce_half(3, 1);              // g=31 npass1
    __syncthreads();

    // ================= output projection =================
    {
        float* sUo = (float*)(smem + OFF_SA);           // 16384 floats
        float* sBo = (float*)(smem + OFF_SB);           // 1024 floats
        #pragma unroll
        for (int i = 0; i < 16; i++) {
            int idx = tid + i * 256;
            ((float4*)sUo)[idx] = __ldg((const float4*)Uo + idx);
        }
        ((float4*)sBo)[tid] = __ldg((const float4*)bo + tid);
        __syncthreads();
        #pragma unroll 1
        for (int half = 0; half < 2; half++) {
            const int a = (tid >> 7) + 2 * half, h2 = (tid & 127) * 2;
            float2 uo[16];
            #pragma unroll
            for (int r = 0; r < 16; r++)
                uo[r] = *(float2*)(sUo + (a * 16 + r) * 256 + h2);
            float2 b2 = *(float2*)(sBo + a * 256 + h2);
            #pragma unroll 2
            for (int m = 0; m < 128; m++) {
                float sx = b2.x, sy = b2.y;
                const float* vr = sV + m * SV_P + a * 16;
                #pragma unroll
                for (int r = 0; r < 16; r++) {
                    float vvv = vr[r];
                    sx += vvv * uo[r].x; sy += vvv * uo[r].y;
                }
                *(float2*)(out + (size_t)(b0 + m) * 1024 + a * 256 + h2) = make_float2(sx, sy);
            }
        }
    }
}

extern "C" void kernel_launch(void* const* d_in, const int* in_sizes, int n_in,
                              void* d_out, int out_size) {
    const float* nh = (const float*)d_in[0];
    const float* te = (const float*)d_in[1];
    const float* U  = (const float*)d_in[2];
    const float* bB = (const float*)d_in[3];
    const float* Ut = (const float*)d_in[4];
    const float* bt = (const float*)d_in[5];
    const float* Uo = (const float*)d_in[6];
    const float* bo = (const float*)d_in[7];
    float* out = (float*)d_out;

    prep_A<<<8192, 256>>>(nh);
    prep_B<<<512, 256>>>(U);
    cudaFuncSetAttribute(tt_main, cudaFuncAttributeMaxDynamicSharedMemorySize, SMEM_SZ);
    tt_main<<<128, 256, SMEM_SZ>>>(te, bB, Ut, bt, Uo, bo, out);
}

// round 8
// speedup vs baseline: 1.0821x; 1.0821x over previous
#include <cuda_runtime.h>
#include <cuda_bf16.h>
#include <cstdint>

#define NG 32
#define SV_P 68
#define RED_P 18

// A fragments hi/lo interleaved: [c(8)][mt(1024)][kt(16)][lane(32)] x {hi,lo} uint4
__device__ uint4 g_Af[8 * 1024 * 16 * 32 * 2];
// B fragments hi/lo interleaved: [g(32)][kt(16)][nt(32)][lane(32)] uint4 {h0,h1,l0,l1}
__device__ uint4 g_Bf[NG * 16 * 32 * 32];

// ---- smem map (bytes), per CTA (M=64) ----
#define OFF_BIAS 0          // 1024
#define OFF_SV   1024       // 64*68*4 = 17408
#define OFF_RED  18432      // 4*64*18*4 = 18432  (also v0's sTe scratch, 16 KB)
#define OFF_SA   36864      // 2 x 8192  (hi 4K | lo 4K per buf)
#define OFF_SB   53248      // 2 x 16384
#define SMEM_SZ  86016

__device__ __forceinline__ uint32_t s2u(const void* p) {
    uint32_t a;
    asm("{ .reg .u64 t; cvta.to.shared.u64 t, %1; cvt.u32.u64 %0, t; }" : "=r"(a) : "l"(p));
    return a;
}
__device__ __forceinline__ uint32_t pack_hi(float x, float y) {
    __nv_bfloat162 h = __halves2bfloat162(__float2bfloat16(x), __float2bfloat16(y));
    return *(uint32_t*)&h;
}
__device__ __forceinline__ uint32_t pack_lo(float x, float y, uint32_t hb) {
    __nv_bfloat162 h = *(__nv_bfloat162*)&hb;
    __nv_bfloat162 lo = __halves2bfloat162(
        __float2bfloat16(x - __bfloat162float(h.x)),
        __float2bfloat16(y - __bfloat162float(h.y)));
    return *(uint32_t*)&lo;
}
__device__ __forceinline__ void mma_bf16(float* c, const uint32_t* a, uint32_t b0, uint32_t b1) {
    asm volatile(
        "mma.sync.aligned.m16n8k16.row.col.f32.bf16.bf16.f32 "
        "{%0,%1,%2,%3}, {%4,%5,%6,%7}, {%8,%9}, {%0,%1,%2,%3};"
        : "+f"(c[0]), "+f"(c[1]), "+f"(c[2]), "+f"(c[3])
        : "r"(a[0]), "r"(a[1]), "r"(a[2]), "r"(a[3]), "r"(b0), "r"(b1));
}
__device__ __forceinline__ void cpa16(uint32_t dst, const void* src) {
    asm volatile("cp.async.cg.shared.global [%0], [%1], 16;" :: "r"(dst), "l"(src) : "memory");
}
#define CP_COMMIT() asm volatile("cp.async.commit_group;" ::: "memory")
#define CP_WAIT0()  asm volatile("cp.async.wait_group 0;" ::: "memory")

// ---------------- prep_A: nh f32 -> A fragments hi/lo interleaved ----------------
__global__ __launch_bounds__(256) void prep_A(const float* __restrict__ nh) {
    const int blk = blockIdx.x;              // 8192 = c(8) x mt(1024)
    const int c = blk >> 10, mt = blk & 1023;
    #pragma unroll
    for (int s = 0; s < 2; s++) {
        int u = threadIdx.x + s * 256;       // kt(16) x lane(32)
        int kt = u >> 5, l = u & 31;
        int row = mt * 16 + (l >> 2);
        int k = kt * 16 + (l & 3) * 2;
        const float* p = nh + ((size_t)row * 8 + c) * 256 + k;
        float2 x0 = __ldg((const float2*)p);
        float2 x1 = __ldg((const float2*)(p + 8 * 2048));
        float2 x2 = __ldg((const float2*)(p + 8));
        float2 x3 = __ldg((const float2*)(p + 8 * 2048 + 8));
        uint32_t h0 = pack_hi(x0.x, x0.y), h1 = pack_hi(x1.x, x1.y);
        uint32_t h2 = pack_hi(x2.x, x2.y), h3 = pack_hi(x3.x, x3.y);
        size_t o = ((size_t)(c * 1024 + mt) * 16 + kt) * 32 + l;
        g_Af[2 * o]     = make_uint4(h0, h1, h2, h3);
        g_Af[2 * o + 1] = make_uint4(pack_lo(x0.x, x0.y, h0), pack_lo(x1.x, x1.y, h1),
                                     pack_lo(x2.x, x2.y, h2), pack_lo(x3.x, x3.y, h3));
    }
}

// ---------------- prep_B: U f32 -> B fragments hi/lo interleaved ----------------
__global__ __launch_bounds__(256) void prep_B(const float* __restrict__ U) {
    const int blk = blockIdx.x;              // 512 = g(32) x kt(16)
    const int g = blk >> 4, kt = blk & 15;
    const float* Ug = U + (size_t)g * 256 * 272;
    #pragma unroll
    for (int s = 0; s < 4; s++) {
        int u = threadIdx.x + s * 256;       // nt(32) x lane(32)
        int nt = u >> 5, l = u & 31;
        int k0 = kt * 16 + (l & 3) * 2, n0 = nt * 8 + (l >> 2);
        float u0 = __ldg(Ug + (size_t)k0 * 272 + n0);
        float u1 = __ldg(Ug + (size_t)(k0 + 1) * 272 + n0);
        float u8 = __ldg(Ug + (size_t)(k0 + 8) * 272 + n0);
        float u9 = __ldg(Ug + (size_t)(k0 + 9) * 272 + n0);
        uint32_t h0 = pack_hi(u0, u1), h1 = pack_hi(u8, u9);
        uint32_t l0 = pack_lo(u0, u1, h0), l1 = pack_lo(u8, u9, h1);
        g_Bf[((size_t)(g * 16 + kt) * 32 + nt) * 32 + l] = make_uint4(h0, h1, l0, l1);
    }
}

// ---- main: 256 CTAs x 256 threads (8 warps: mw2 x nwp4, warp tile 32x32), 2 CTAs/SM ----
__global__ __launch_bounds__(256, 2)
void tt_main(const float* __restrict__ te, const float* __restrict__ bB,
             const float* __restrict__ Ut, const float* __restrict__ bt,
             const float* __restrict__ Uo, const float* __restrict__ bo,
             float* __restrict__ out)
{
    extern __shared__ __align__(16) char smem[];
    const uint32_t sbase = s2u(smem);
    float* sBias = (float*)(smem + OFF_BIAS);
    float* sV    = (float*)(smem + OFF_SV);
    float* red   = (float*)(smem + OFF_RED);

    const int tid = threadIdx.x;
    const int l   = tid & 31, w = tid >> 5;
    const int mw  = w >> 2,  nwp = w & 3;       // warp grid 2M x 4N over 64 rows
    const int b0  = blockIdx.x * 64;
    const int mt0 = blockIdx.x * 4;             // m-tiles of 16

    // ================= v0 = te @ U_type + b_type =================
    {
        float* sUt = (float*)(smem + OFF_SA);   // 4096 floats = 16 KB
        float* sTe = red;                       // 64x64 floats, rotated
        #pragma unroll
        for (int i = 0; i < 4; i++) {
            int idx = tid + i * 256;
            ((float4*)sUt)[idx] = __ldg((const float4*)Ut + idx);
        }
        #pragma unroll
        for (int i = 0; i < 4; i++) {
            int u = tid + i * 256;              // 1024 float4 units
            int m = u >> 4, t4 = u & 15;
            *(float4*)(sTe + m * 64 + ((t4 + m) & 15) * 4) =
                __ldg((const float4*)(te + (size_t)(b0 + m) * 64) + t4);
        }
        __syncthreads();
        const int m = tid & 63, aa = tid >> 6;
        float4 q0 = __ldg((const float4*)(bt + aa * 16) + 0);
        float4 q1 = __ldg((const float4*)(bt + aa * 16) + 1);
        float4 q2 = __ldg((const float4*)(bt + aa * 16) + 2);
        float4 q3 = __ldg((const float4*)(bt + aa * 16) + 3);
        float vv[16] = {q0.x,q0.y,q0.z,q0.w, q1.x,q1.y,q1.z,q1.w,
                        q2.x,q2.y,q2.z,q2.w, q3.x,q3.y,q3.z,q3.w};
        #pragma unroll 4
        for (int t4 = 0; t4 < 16; t4++) {
            float4 xv = *(float4*)(sTe + m * 64 + ((t4 + m) & 15) * 4);
            float xs[4] = {xv.x, xv.y, xv.z, xv.w};
            #pragma unroll
            for (int e = 0; e < 4; e++) {
                float x = xs[e];
                const float4* ur = (const float4*)(sUt + aa * 1024 + (t4 * 4 + e) * 16);
                float4 u0 = ur[0], u1 = ur[1], u2 = ur[2], u3 = ur[3];
                vv[0]+=x*u0.x; vv[1]+=x*u0.y; vv[2]+=x*u0.z; vv[3]+=x*u0.w;
                vv[4]+=x*u1.x; vv[5]+=x*u1.y; vv[6]+=x*u1.z; vv[7]+=x*u1.w;
                vv[8]+=x*u2.x; vv[9]+=x*u2.y; vv[10]+=x*u2.z; vv[11]+=x*u2.w;
                vv[12]+=x*u3.x; vv[13]+=x*u3.y; vv[14]+=x*u3.z; vv[15]+=x*u3.w;
            }
        }
        #pragma unroll
        for (int j = 0; j < 16; j++) sV[m * SV_P + aa * 16 + j] = vv[j];
        __syncthreads();
    }

    // ================= pipeline: 512 chunks (g32 x npass2 x kc8), KC=32 =================
    auto issue = [&](int q) {
        const int g = q >> 4, npass = (q >> 3) & 1, kc = q & 7, buf = q & 1;
        const int c = g >> 2;
        const uint32_t aDst = sbase + OFF_SA + buf * 8192;
        {
            int u = tid;                        // 256: mtL(4) x ktL(2) x l(32)
            int mtL = u >> 6, ktL = (u >> 5) & 1, ll = u & 31;
            size_t o = ((size_t)(c * 1024 + mt0 + mtL) * 16 + kc * 2 + ktL) * 32 + ll;
            cpa16(aDst + u * 16,        g_Af + 2 * o);
            cpa16(aDst + 4096 + u * 16, g_Af + 2 * o + 1);
        }
        const uint32_t bDst = sbase + OFF_SB + buf * 16384;
        #pragma unroll
        for (int s = 0; s < 4; s++) {
            int u = tid + s * 256;              // 1024: ktL(2) x ntL(16) x l(32)
            int ktL = u >> 9, ntL = (u >> 5) & 15, ll = u & 31;
            size_t o = ((size_t)(g * 16 + kc * 2 + ktL) * 32 + npass * 16 + ntL) * 32 + ll;
            cpa16(bDst + u * 16, g_Bf + o);
        }
        CP_COMMIT();
    };

    float nvp[4] = {0.f, 0.f, 0.f, 0.f};
    auto reduce_half = [&](int aP, int doStore) {
        int row = tid & 63, jq = tid >> 6;
        #pragma unroll
        for (int e = 0; e < 4; e++) {
            float s = red[(0 * 64 + row) * RED_P + jq * 4 + e]
                    + red[(1 * 64 + row) * RED_P + jq * 4 + e]
                    + red[(2 * 64 + row) * RED_P + jq * 4 + e]
                    + red[(3 * 64 + row) * RED_P + jq * 4 + e];
            nvp[e] += s;
            if (doStore) {
                sV[row * SV_P + aP * 16 + jq * 4 + e] = nvp[e];
                nvp[e] = 0.f;
            }
        }
    };

    issue(0);

    float acc[2][4][4];   // mt x nt x frag

    #pragma unroll 1
    for (int q = 0; q < 512; q++) {
        const int g = q >> 4, npass = (q >> 3) & 1, kc = q & 7, buf = q & 1;
        const int a = g & 3;

        CP_WAIT0();
        __syncthreads();
        if (q + 1 < 512) issue(q + 1);

        if ((q & 15) == 8)           reduce_half(0, 0);
        else if ((q & 15) == 0 && q) reduce_half((g - 1) & 3, 1);

        if (kc == 0 && npass == 0 && tid < 64)
            ((float4*)sBias)[tid] = __ldg((const float4*)(bB + (size_t)g * 272) + tid);
        if (kc == 0) {
            #pragma unroll
            for (int mt = 0; mt < 2; mt++)
                #pragma unroll
                for (int nt = 0; nt < 4; nt++)
                    #pragma unroll
                    for (int e = 0; e < 4; e++) acc[mt][nt][e] = 0.f;
        }

        // ---- compute 2 k-tiles ----
        const char* sAb = smem + OFF_SA + buf * 8192;
        const char* sBb = smem + OFF_SB + buf * 16384;
        #pragma unroll
        for (int ktL = 0; ktL < 2; ktL++) {
            uint32_t Ah[2][4], Al[2][4];
            #pragma unroll
            for (int mt = 0; mt < 2; mt++) {
                int mtL = mw * 2 + mt;
                *(uint4*)Ah[mt] = *(const uint4*)(sAb + ((mtL * 2 + ktL) * 32 + l) * 16);
                *(uint4*)Al[mt] = *(const uint4*)(sAb + 4096 + ((mtL * 2 + ktL) * 32 + l) * 16);
            }
            uint4 Bq[4];
            #pragma unroll
            for (int nt = 0; nt < 4; nt++)
                Bq[nt] = *(const uint4*)(sBb + ((ktL * 16 + nwp * 4 + nt) * 32 + l) * 16);
            #pragma unroll
            for (int nt = 0; nt < 4; nt++)
                #pragma unroll
                for (int mt = 0; mt < 2; mt++)
                    mma_bf16(acc[mt][nt], Ah[mt], Bq[nt].x, Bq[nt].y);
            #pragma unroll
            for (int nt = 0; nt < 4; nt++)
                #pragma unroll
                for (int mt = 0; mt < 2; mt++)
                    mma_bf16(acc[mt][nt], Ah[mt], Bq[nt].z, Bq[nt].w);
            #pragma unroll
            for (int nt = 0; nt < 4; nt++)
                #pragma unroll
                for (int mt = 0; mt < 2; mt++)
                    mma_bf16(acc[mt][nt], Al[mt], Bq[nt].x, Bq[nt].y);
        }

        // ---- epilogue: write scan partials (reduction deferred past next barrier) ----
        if (kc == 7) {
            const int i0 = npass * 8 + nwp * 2, i1 = i0 + 1;
            const int j0 = (l & 3) * 2;
            float2 b00 = *(float2*)(sBias + i0 * 16 + j0);
            float2 b01 = *(float2*)(sBias + i1 * 16 + j0);
            float2 b10 = *(float2*)(sBias + i0 * 16 + j0 + 8);
            float2 b11 = *(float2*)(sBias + i1 * 16 + j0 + 8);
            const float add1 = (i1 == 15) ? 1.f : 0.f;
            const int rbase = mw * 32 + (l >> 2);
            #pragma unroll
            for (int p = 0; p < 4; p++) {
                int row = rbase + p * 8;
                int mt = p >> 1, h = (p & 1) * 2;
                float c0 = sV[row * SV_P + a * 16 + i0];
                float c1 = sV[row * SV_P + a * 16 + i1] + add1;
                float2 pj, pk;
                pj.x = c0 * (acc[mt][0][h+0] + b00.x) + c1 * (acc[mt][2][h+0] + b01.x);
                pj.y = c0 * (acc[mt][0][h+1] + b00.y) + c1 * (acc[mt][2][h+1] + b01.y);
                pk.x = c0 * (acc[mt][1][h+0] + b10.x) + c1 * (acc[mt][3][h+0] + b11.x);
                pk.y = c0 * (acc[mt][1][h+1] + b10.y) + c1 * (acc[mt][3][h+1] + b11.y);
                *(float2*)(red + (nwp * 64 + row) * RED_P + j0)     = pj;
                *(float2*)(red + (nwp * 64 + row) * RED_P + j0 + 8) = pk;
            }
        }
    }

    __syncthreads();                // final partials (g=31, npass=1) visible
    reduce_half(3, 1);
    __syncthreads();

    // ================= output projection (Uo/bo straight from L2) =================
    {
        const int a = tid >> 6, c4 = (tid & 63) * 4;
        float4 uo[16];
        #pragma unroll
        for (int r = 0; r < 16; r++)
            uo[r] = __ldg((const float4*)(Uo + ((size_t)a * 16 + r) * 256 + c4));
        float4 b4 = __ldg((const float4*)(bo + a * 256 + c4));
        #pragma unroll 2
        for (int m = 0; m < 64; m++) {
            float4 s = b4;
            const float4* vr = (const float4*)(sV + m * SV_P + a * 16);
            float4 v0 = vr[0], v1 = vr[1], v2 = vr[2], v3 = vr[3];
            float vs[16] = {v0.x,v0.y,v0.z,v0.w, v1.x,v1.y,v1.z,v1.w,
                            v2.x,v2.y,v2.z,v2.w, v3.x,v3.y,v3.z,v3.w};
            #pragma unroll
            for (int r = 0; r < 16; r++) {
                s.x += vs[r] * uo[r].x; s.y += vs[r] * uo[r].y;
                s.z += vs[r] * uo[r].z; s.w += vs[r] * uo[r].w;
            }
            *(float4*)(out + (size_t)(b0 + m) * 1024 + a * 256 + c4) = s;
        }
    }
}

extern "C" void kernel_launch(void* const* d_in, const int* in_sizes, int n_in,
                              void* d_out, int out_size) {
    const float* nh = (const float*)d_in[0];
    const float* te = (const float*)d_in[1];
    const float* U  = (const float*)d_in[2];
    const float* bB = (const float*)d_in[3];
    const float* Ut = (const float*)d_in[4];
    const float* bt = (const float*)d_in[5];
    const float* Uo = (const float*)d_in[6];
    const float* bo = (const float*)d_in[7];
    float* out = (float*)d_out;

    prep_A<<<8192, 256>>>(nh);
    prep_B<<<512, 256>>>(U);
    cudaFuncSetAttribute(tt_main, cudaFuncAttributeMaxDynamicSharedMemorySize, SMEM_SZ);
    tt_main<<<256, 256, SMEM_SZ>>>(te, bB, Ut, bt, Uo, bo, out);
}

// round 10
// speedup vs baseline: 1.2423x; 1.1480x over previous
#include <cuda_runtime.h>
#include <cuda_bf16.h>
#include <cstdint>

#define NG 32
#define SV_P 65
#define RED_P 18

// A fragments hi/lo interleaved: [c(8)][mt(1024)][kt(16)][lane(32)] x {hi,lo} uint4
__device__ uint4 g_Af[8 * 1024 * 16 * 32 * 2];
// B fragments hi/lo interleaved: [g(32)][kt(16)][nt(32)][lane(32)] uint4 {h0,h1,l0,l1}
__device__ uint4 g_Bf[NG * 16 * 32 * 32];

// ---- smem map (bytes) ----
#define OFF_BIAS 0          // 1024
#define OFF_SV   1024       // 128*65*4 = 33280
#define OFF_RED  34304      // 4*128*18*4 = 36864 (also v0's sTe scratch)
#define OFF_SA   71168      // 2 x 16384 (hi 8K | lo 8K per buf)
#define OFF_SB   103936     // 2 x 32768
#define SMEM_SZ  169472

__device__ __forceinline__ uint32_t s2u(const void* p) {
    uint32_t a;
    asm("{ .reg .u64 t; cvta.to.shared.u64 t, %1; cvt.u32.u64 %0, t; }" : "=r"(a) : "l"(p));
    return a;
}
__device__ __forceinline__ uint32_t pack_hi(float x, float y) {
    __nv_bfloat162 h = __halves2bfloat162(__float2bfloat16(x), __float2bfloat16(y));
    return *(uint32_t*)&h;
}
__device__ __forceinline__ uint32_t pack_lo(float x, float y, uint32_t hb) {
    __nv_bfloat162 h = *(__nv_bfloat162*)&hb;
    __nv_bfloat162 lo = __halves2bfloat162(
        __float2bfloat16(x - __bfloat162float(h.x)),
        __float2bfloat16(y - __bfloat162float(h.y)));
    return *(uint32_t*)&lo;
}
__device__ __forceinline__ void mma_bf16(float* c, const uint32_t* a, uint32_t b0, uint32_t b1) {
    asm volatile(
        "mma.sync.aligned.m16n8k16.row.col.f32.bf16.bf16.f32 "
        "{%0,%1,%2,%3}, {%4,%5,%6,%7}, {%8,%9}, {%0,%1,%2,%3};"
        : "+f"(c[0]), "+f"(c[1]), "+f"(c[2]), "+f"(c[3])
        : "r"(a[0]), "r"(a[1]), "r"(a[2]), "r"(a[3]), "r"(b0), "r"(b1));
}
__device__ __forceinline__ void cpa16(uint32_t dst, const void* src) {
    asm volatile("cp.async.cg.shared.global [%0], [%1], 16;" :: "r"(dst), "l"(src) : "memory");
}
#define CP_COMMIT() asm volatile("cp.async.commit_group;" ::: "memory")
#define CP_WAIT0()  asm volatile("cp.async.wait_group 0;" ::: "memory")

// ---------------- prep_A: nh f32 -> A fragments hi/lo interleaved ----------------
__global__ __launch_bounds__(256) void prep_A(const float* __restrict__ nh) {
    const int blk = blockIdx.x;              // 8192 = c(8) x mt(1024)
    const int c = blk >> 10, mt = blk & 1023;
    #pragma unroll
    for (int s = 0; s < 2; s++) {
        int u = threadIdx.x + s * 256;       // kt(16) x lane(32)
        int kt = u >> 5, l = u & 31;
        int row = mt * 16 + (l >> 2);
        int k = kt * 16 + (l & 3) * 2;
        const float* p = nh + ((size_t)row * 8 + c) * 256 + k;
        float2 x0 = __ldg((const float2*)p);
        float2 x1 = __ldg((const float2*)(p + 8 * 2048));
        float2 x2 = __ldg((const float2*)(p + 8));
        float2 x3 = __ldg((const float2*)(p + 8 * 2048 + 8));
        uint32_t h0 = pack_hi(x0.x, x0.y), h1 = pack_hi(x1.x, x1.y);
        uint32_t h2 = pack_hi(x2.x, x2.y), h3 = pack_hi(x3.x, x3.y);
        size_t o = ((size_t)(c * 1024 + mt) * 16 + kt) * 32 + l;
        g_Af[2 * o]     = make_uint4(h0, h1, h2, h3);
        g_Af[2 * o + 1] = make_uint4(pack_lo(x0.x, x0.y, h0), pack_lo(x1.x, x1.y, h1),
                                     pack_lo(x2.x, x2.y, h2), pack_lo(x3.x, x3.y, h3));
    }
}

// ---------------- prep_B: U f32 -> B fragments hi/lo interleaved ----------------
__global__ __launch_bounds__(256) void prep_B(const float* __restrict__ U) {
    const int blk = blockIdx.x;              // 512 = g(32) x kt(16)
    const int g = blk >> 4, kt = blk & 15;
    const float* Ug = U + (size_t)g * 256 * 272;
    #pragma unroll
    for (int s = 0; s < 4; s++) {
        int u = threadIdx.x + s * 256;       // nt(32) x lane(32)
        int nt = u >> 5, l = u & 31;
        int k0 = kt * 16 + (l & 3) * 2, n0 = nt * 8 + (l >> 2);
        float u0 = __ldg(Ug + (size_t)k0 * 272 + n0);
        float u1 = __ldg(Ug + (size_t)(k0 + 1) * 272 + n0);
        float u8 = __ldg(Ug + (size_t)(k0 + 8) * 272 + n0);
        float u9 = __ldg(Ug + (size_t)(k0 + 9) * 272 + n0);
        uint32_t h0 = pack_hi(u0, u1), h1 = pack_hi(u8, u9);
        uint32_t l0 = pack_lo(u0, u1, h0), l1 = pack_lo(u8, u9, h1);
        g_Bf[((size_t)(g * 16 + kt) * 32 + nt) * 32 + l] = make_uint4(h0, h1, l0, l1);
    }
}

// ---- main: 128 CTAs x 512 threads (16 warps: mw4 x nwp4), KC=32, full N=256/chunk ----
__global__ __launch_bounds__(512, 1)
void tt_main(const float* __restrict__ te, const float* __restrict__ bB,
             const float* __restrict__ Ut, const float* __restrict__ bt,
             const float* __restrict__ Uo, const float* __restrict__ bo,
             float* __restrict__ out)
{
    extern __shared__ __align__(16) char smem[];
    const uint32_t sbase = s2u(smem);
    float* sBias = (float*)(smem + OFF_BIAS);
    float* sV    = (float*)(smem + OFF_SV);
    float* red   = (float*)(smem + OFF_RED);

    const int tid = threadIdx.x;
    const int l   = tid & 31, w = tid >> 5;
    const int mw  = w >> 2,  nwp = w & 3;       // warp grid 4M x 4N
    const int b0  = blockIdx.x * 128;
    const int mt0 = blockIdx.x * 8;

    // ================= v0 = te @ U_type + b_type =================
    {
        float* sUt = (float*)(smem + OFF_SA);   // 4096 floats
        float* sTe = red;                       // 128x64, float4-rotated (32 KB)
        #pragma unroll
        for (int i = 0; i < 2; i++) {
            int idx = tid + i * 512;
            ((float4*)sUt)[idx] = __ldg((const float4*)Ut + idx);
        }
        #pragma unroll
        for (int i = 0; i < 4; i++) {
            int u = tid + i * 512;              // 2048 float4 units
            int m = u >> 4, t4 = u & 15;
            *(float4*)(sTe + m * 64 + ((t4 + m) & 15) * 4) =
                __ldg((const float4*)(te + (size_t)(b0 + m) * 64) + t4);
        }
        __syncthreads();
        const int m = tid & 127, aa = tid >> 7;
        float4 q0 = __ldg((const float4*)(bt + aa * 16) + 0);
        float4 q1 = __ldg((const float4*)(bt + aa * 16) + 1);
        float4 q2 = __ldg((const float4*)(bt + aa * 16) + 2);
        float4 q3 = __ldg((const float4*)(bt + aa * 16) + 3);
        float vv[16] = {q0.x,q0.y,q0.z,q0.w, q1.x,q1.y,q1.z,q1.w,
                        q2.x,q2.y,q2.z,q2.w, q3.x,q3.y,q3.z,q3.w};
        #pragma unroll 4
        for (int t4 = 0; t4 < 16; t4++) {
            float4 xv = *(float4*)(sTe + m * 64 + ((t4 + m) & 15) * 4);
            float xs[4] = {xv.x, xv.y, xv.z, xv.w};
            #pragma unroll
            for (int e = 0; e < 4; e++) {
                float x = xs[e];
                const float4* ur = (const float4*)(sUt + aa * 1024 + (t4 * 4 + e) * 16);
                float4 u0 = ur[0], u1 = ur[1], u2 = ur[2], u3 = ur[3];
                vv[0]+=x*u0.x; vv[1]+=x*u0.y; vv[2]+=x*u0.z; vv[3]+=x*u0.w;
                vv[4]+=x*u1.x; vv[5]+=x*u1.y; vv[6]+=x*u1.z; vv[7]+=x*u1.w;
                vv[8]+=x*u2.x; vv[9]+=x*u2.y; vv[10]+=x*u2.z; vv[11]+=x*u2.w;
                vv[12]+=x*u3.x; vv[13]+=x*u3.y; vv[14]+=x*u3.z; vv[15]+=x*u3.w;
            }
        }
        #pragma unroll
        for (int j = 0; j < 16; j++) sV[m * SV_P + aa * 16 + j] = vv[j];
        __syncthreads();
    }

    // ================= pipeline: 256 chunks (g32 x kc8), KC=32, N=256 =================
    auto issue = [&](int q) {
        const int g = q >> 3, kc = q & 7, buf = q & 1;
        const int c = g >> 2;
        const uint32_t aDst = sbase + OFF_SA + buf * 16384;
        {
            int mtL = tid >> 6, ktL = (tid >> 5) & 1, ll = tid & 31;
            size_t o = ((size_t)(c * 1024 + mt0 + mtL) * 16 + kc * 2 + ktL) * 32 + ll;
            cpa16(aDst + tid * 16,        g_Af + 2 * o);
            cpa16(aDst + 8192 + tid * 16, g_Af + 2 * o + 1);
        }
        const uint32_t bDst = sbase + OFF_SB + buf * 32768;
        #pragma unroll
        for (int s = 0; s < 4; s++) {
            int u = tid + s * 512;              // 2048: ktL(2) x ntF(32) x l(32)
            int ktL = u >> 10, ntF = (u >> 5) & 31, ll = u & 31;
            size_t o = ((size_t)(g * 16 + kc * 2 + ktL) * 32 + ntF) * 32 + ll;
            cpa16(bDst + u * 16, g_Bf + o);
        }
        CP_COMMIT();
    };

    auto reduce_g = [&](int aP) {   // single-shot: partials from 4 nwp cover all 16 i
        int row = tid & 127, jq = tid >> 7;
        #pragma unroll
        for (int e = 0; e < 4; e++) {
            float s = red[(0 * 128 + row) * RED_P + jq * 4 + e]
                    + red[(1 * 128 + row) * RED_P + jq * 4 + e]
                    + red[(2 * 128 + row) * RED_P + jq * 4 + e]
                    + red[(3 * 128 + row) * RED_P + jq * 4 + e];
            sV[row * SV_P + aP * 16 + jq * 4 + e] = s;
        }
    };

    issue(0);

    float acc[2][2][4][4];   // mt x npass x nt x frag  (64 regs)

    #pragma unroll 1
    for (int q = 0; q < 256; q++) {
        const int g = q >> 3, kc = q & 7, buf = q & 1;
        const int a = g & 3;

        CP_WAIT0();
        __syncthreads();
        if (q + 1 < 256) issue(q + 1);

        if (kc == 2 && q >= 8) reduce_g((g - 1) & 3);

        if (kc == 0) {
            if (tid < 64)
                ((float4*)sBias)[tid] = __ldg((const float4*)(bB + (size_t)g * 272) + tid);
            #pragma unroll
            for (int mt = 0; mt < 2; mt++)
                #pragma unroll
                for (int p = 0; p < 2; p++)
                    #pragma unroll
                    for (int nt = 0; nt < 4; nt++)
                        #pragma unroll
                        for (int e = 0; e < 4; e++) acc[mt][p][nt][e] = 0.f;
        }

        // ---- compute: 2 k-tiles x full N ----
        const char* sAb = smem + OFF_SA + buf * 16384;
        const char* sBb = smem + OFF_SB + buf * 32768;
        #pragma unroll
        for (int ktL = 0; ktL < 2; ktL++) {
            uint32_t Ah[2][4], Al[2][4];
            #pragma unroll
            for (int mt = 0; mt < 2; mt++) {
                int mtL = mw * 2 + mt;
                *(uint4*)Ah[mt] = *(const uint4*)(sAb + ((mtL * 2 + ktL) * 32 + l) * 16);
                *(uint4*)Al[mt] = *(const uint4*)(sAb + 8192 + ((mtL * 2 + ktL) * 32 + l) * 16);
            }
            #pragma unroll
            for (int p = 0; p < 2; p++) {
                uint4 Bq[4];
                #pragma unroll
                for (int nt = 0; nt < 4; nt++)
                    Bq[nt] = *(const uint4*)(sBb +
                        ((ktL * 32 + p * 16 + nwp * 4 + nt) * 32 + l) * 16);
                #pragma unroll
                for (int nt = 0; nt < 4; nt++)
                    #pragma unroll
                    for (int mt = 0; mt < 2; mt++)
                        mma_bf16(acc[mt][p][nt], Ah[mt], Bq[nt].x, Bq[nt].y);
                #pragma unroll
                for (int nt = 0; nt < 4; nt++)
                    #pragma unroll
                    for (int mt = 0; mt < 2; mt++)
                        mma_bf16(acc[mt][p][nt], Ah[mt], Bq[nt].z, Bq[nt].w);
                #pragma unroll
                for (int nt = 0; nt < 4; nt++)
                    #pragma unroll
                    for (int mt = 0; mt < 2; mt++)
                        mma_bf16(acc[mt][p][nt], Al[mt], Bq[nt].x, Bq[nt].y);
            }
        }

        // ---- epilogue: all 16 scan components for this g ----
        if (kc == 7) {
            const int i00 = nwp * 2, i01 = i00 + 1, i10 = i00 + 8, i11 = i00 + 9;
            const int j0 = (l & 3) * 2;
            float2 bA0  = *(float2*)(sBias + i00 * 16 + j0);
            float2 bA1  = *(float2*)(sBias + i01 * 16 + j0);
            float2 bA0h = *(float2*)(sBias + i00 * 16 + j0 + 8);
            float2 bA1h = *(float2*)(sBias + i01 * 16 + j0 + 8);
            float2 bB0  = *(float2*)(sBias + i10 * 16 + j0);
            float2 bB1  = *(float2*)(sBias + i11 * 16 + j0);
            float2 bB0h = *(float2*)(sBias + i10 * 16 + j0 + 8);
            float2 bB1h = *(float2*)(sBias + i11 * 16 + j0 + 8);
            const float add1 = (i11 == 15) ? 1.f : 0.f;
            const int rbase = mw * 32 + (l >> 2);
            #pragma unroll
            for (int pp = 0; pp < 4; pp++) {
                int row = rbase + pp * 8;
                int mt = pp >> 1, h = (pp & 1) * 2;
                float c00 = sV[row * SV_P + a * 16 + i00];
                float c01 = sV[row * SV_P + a * 16 + i01];
                float c10 = sV[row * SV_P + a * 16 + i10];
                float c11 = sV[row * SV_P + a * 16 + i11] + add1;
                float2 pj, pk;
                pj.x = c00 * (acc[mt][0][0][h+0] + bA0.x) + c01 * (acc[mt][0][2][h+0] + bA1.x)
                     + c10 * (acc[mt][1][0][h+0] + bB0.x) + c11 * (acc[mt][1][2][h+0] + bB1.x);
                pj.y = c00 * (acc[mt][0][0][h+1] + bA0.y) + c01 * (acc[mt][0][2][h+1] + bA1.y)
                     + c10 * (acc[mt][1][0][h+1] + bB0.y) + c11 * (acc[mt][1][2][h+1] + bB1.y);
                pk.x = c00 * (acc[mt][0][1][h+0] + bA0h.x) + c01 * (acc[mt][0][3][h+0] + bA1h.x)
                     + c10 * (acc[mt][1][1][h+0] + bB0h.x) + c11 * (acc[mt][1][3][h+0] + bB1h.x);
                pk.y = c00 * (acc[mt][0][1][h+1] + bA0h.y) + c01 * (acc[mt][0][3][h+1] + bA1h.y)
                     + c10 * (acc[mt][1][1][h+1] + bB0h.y) + c11 * (acc[mt][1][3][h+1] + bB1h.y);
                *(float2*)(red + (nwp * 128 + row) * RED_P + j0)     = pj;
                *(float2*)(red + (nwp * 128 + row) * RED_P + j0 + 8) = pk;
            }
        }
    }

    __syncthreads();                // g=31 partials visible
    reduce_g(3);
    __syncthreads();

    // ================= output projection (single pass: a = tid>>7 covers 0..3) ========
    {
        float* sUo = (float*)(smem + OFF_SA);           // 16384 floats (64 KB overlay)
        float* sBo = (float*)(smem + OFF_SA + 65536);   // 1024 floats
        #pragma unroll
        for (int i = 0; i < 8; i++) {
            int idx = tid + i * 512;
            ((float4*)sUo)[idx] = __ldg((const float4*)Uo + idx);
        }
        if (tid < 256) ((float4*)sBo)[tid] = __ldg((const float4*)bo + tid);
        __syncthreads();
        const int a = tid >> 7, h2 = (tid & 127) * 2;   // a in 0..3, 128 col-pairs
        float2 uo[16];
        #pragma unroll
        for (int r = 0; r < 16; r++)
            uo[r] = *(float2*)(sUo + (a * 16 + r) * 256 + h2);
        float2 b2 = *(float2*)(sBo + a * 256 + h2);
        #pragma unroll 2
        for (int m = 0; m < 128; m++) {
            float sx = b2.x, sy = b2.y;
            const float* vr = sV + m * SV_P + a * 16;
            #pragma unroll
            for (int r = 0; r < 16; r++) {
                float vvv = vr[r];
                sx += vvv * uo[r].x; sy += vvv * uo[r].y;
            }
            *(float2*)(out + (size_t)(b0 + m) * 1024 + a * 256 + h2) = make_float2(sx, sy);
        }
    }
}

extern "C" void kernel_launch(void* const* d_in, const int* in_sizes, int n_in,
                              void* d_out, int out_size) {
    const float* nh = (const float*)d_in[0];
    const float* te = (const float*)d_in[1];
    const float* U  = (const float*)d_in[2];
    const float* bB = (const float*)d_in[3];
    const float* Ut = (const float*)d_in[4];
    const float* bt = (const float*)d_in[5];
    const float* Uo = (const float*)d_in[6];
    const float* bo = (const float*)d_in[7];
    float* out = (float*)d_out;

    prep_A<<<8192, 256>>>(nh);
    prep_B<<<512, 256>>>(U);
    cudaFuncSetAttribute(tt_main, cudaFuncAttributeMaxDynamicSharedMemorySize, SMEM_SZ);
    tt_main<<<128, 512, SMEM_SZ>>>(te, bB, Ut, bt, Uo, bo, out);
}

// round 11
// speedup vs baseline: 2.8053x; 2.2581x over previous
#include <cuda_runtime.h>
#include <cuda_fp16.h>
#include <cstdint>

#define NG 32
#define SV_P 65
#define RED_P 18

// A fragments fp16: [c(8)][mt(1024)][kt(16)][lane(32)] uint4 {a0,a1,a2,a3}
__device__ uint4 g_Af[8 * 1024 * 16 * 32];
// B fragments fp16: [g(32)][kt(16)][nt(32)][lane(32)] uint2 {b0,b1}
__device__ uint2 g_Bf[NG * 16 * 32 * 32];

// ---- smem map (bytes) ----
#define OFF_BIAS 0          // 1024
#define OFF_SV   1024       // 128*65*4 = 33280
#define OFF_RED  34304      // 4*128*18*4 = 36864 (also v0's sTe scratch)
#define OFF_SA   71168      // 2 x 32768
#define OFF_SB   136704     // 2 x 32768
#define SMEM_SZ  202240

__device__ __forceinline__ uint32_t s2u(const void* p) {
    uint32_t a;
    asm("{ .reg .u64 t; cvta.to.shared.u64 t, %1; cvt.u32.u64 %0, t; }" : "=r"(a) : "l"(p));
    return a;
}
__device__ __forceinline__ uint32_t pack_h2(float x, float y) {
    __half2 h = __floats2half2_rn(x, y);
    return *(uint32_t*)&h;
}
__device__ __forceinline__ void mma_f16(float* c, const uint32_t* a, uint32_t b0, uint32_t b1) {
    asm volatile(
        "mma.sync.aligned.m16n8k16.row.col.f32.f16.f16.f32 "
        "{%0,%1,%2,%3}, {%4,%5,%6,%7}, {%8,%9}, {%0,%1,%2,%3};"
        : "+f"(c[0]), "+f"(c[1]), "+f"(c[2]), "+f"(c[3])
        : "r"(a[0]), "r"(a[1]), "r"(a[2]), "r"(a[3]), "r"(b0), "r"(b1));
}
__device__ __forceinline__ void cpa16(uint32_t dst, const void* src) {
    asm volatile("cp.async.cg.shared.global [%0], [%1], 16;" :: "r"(dst), "l"(src) : "memory");
}
#define CP_COMMIT() asm volatile("cp.async.commit_group;" ::: "memory")
#define CP_WAIT0()  asm volatile("cp.async.wait_group 0;" ::: "memory")

// ---------------- prep_A: nh f32 -> fp16 A fragments ----------------
__global__ __launch_bounds__(256) void prep_A(const float* __restrict__ nh) {
    const int blk = blockIdx.x;              // 8192 = c(8) x mt(1024)
    const int c = blk >> 10, mt = blk & 1023;
    #pragma unroll
    for (int s = 0; s < 2; s++) {
        int u = threadIdx.x + s * 256;       // kt(16) x lane(32)
        int kt = u >> 5, l = u & 31;
        int row = mt * 16 + (l >> 2);
        int k = kt * 16 + (l & 3) * 2;
        const float* p = nh + ((size_t)row * 8 + c) * 256 + k;
        float2 x0 = __ldg((const float2*)p);                   // (r,   k)
        float2 x1 = __ldg((const float2*)(p + 8 * 2048));      // (r+8, k)
        float2 x2 = __ldg((const float2*)(p + 8));             // (r,   k+8)
        float2 x3 = __ldg((const float2*)(p + 8 * 2048 + 8));  // (r+8, k+8)
        size_t o = ((size_t)(c * 1024 + mt) * 16 + kt) * 32 + l;
        g_Af[o] = make_uint4(pack_h2(x0.x, x0.y), pack_h2(x1.x, x1.y),
                             pack_h2(x2.x, x2.y), pack_h2(x3.x, x3.y));
    }
}

// ---------------- prep_B: U f32 -> fp16 B fragments ----------------
__global__ __launch_bounds__(256) void prep_B(const float* __restrict__ U) {
    const int blk = blockIdx.x;              // 512 = g(32) x kt(16)
    const int g = blk >> 4, kt = blk & 15;
    const float* Ug = U + (size_t)g * 256 * 272;
    #pragma unroll
    for (int s = 0; s < 4; s++) {
        int u = threadIdx.x + s * 256;       // nt(32) x lane(32)
        int nt = u >> 5, l = u & 31;
        int k0 = kt * 16 + (l & 3) * 2, n0 = nt * 8 + (l >> 2);
        float u0 = __ldg(Ug + (size_t)k0 * 272 + n0);
        float u1 = __ldg(Ug + (size_t)(k0 + 1) * 272 + n0);
        float u8 = __ldg(Ug + (size_t)(k0 + 8) * 272 + n0);
        float u9 = __ldg(Ug + (size_t)(k0 + 9) * 272 + n0);
        g_Bf[((size_t)(g * 16 + kt) * 32 + nt) * 32 + l] =
            make_uint2(pack_h2(u0, u1), pack_h2(u8, u9));
    }
}

// ---- main: 128 CTAs x 512 threads (16 warps: mw4 x nwp4, warp tile 32x32), KC=128 ----
__global__ __launch_bounds__(512, 1)
void tt_main(const float* __restrict__ te, const float* __restrict__ bB,
             const float* __restrict__ Ut, const float* __restrict__ bt,
             const float* __restrict__ Uo, const float* __restrict__ bo,
             float* __restrict__ out)
{
    extern __shared__ __align__(16) char smem[];
    const uint32_t sbase = s2u(smem);
    float* sBias = (float*)(smem + OFF_BIAS);
    float* sV    = (float*)(smem + OFF_SV);
    float* red   = (float*)(smem + OFF_RED);

    const int tid = threadIdx.x;
    const int l   = tid & 31, w = tid >> 5;
    const int mw  = w >> 2,  nwp = w & 3;       // warp grid 4M x 4N
    const int b0  = blockIdx.x * 128;
    const int mt0 = blockIdx.x * 8;

    // ================= v0 = te @ U_type + b_type =================
    {
        float* sUt = (float*)(smem + OFF_SA);   // 4096 floats
        float* sTe = red;                       // 128x64, float4-rotated (32 KB)
        #pragma unroll
        for (int i = 0; i < 2; i++) {
            int idx = tid + i * 512;
            ((float4*)sUt)[idx] = __ldg((const float4*)Ut + idx);
        }
        #pragma unroll
        for (int i = 0; i < 4; i++) {
            int u = tid + i * 512;              // 2048 float4 units
            int m = u >> 4, t4 = u & 15;
            *(float4*)(sTe + m * 64 + ((t4 + m) & 15) * 4) =
                __ldg((const float4*)(te + (size_t)(b0 + m) * 64) + t4);
        }
        __syncthreads();
        const int m = tid & 127, aa = tid >> 7;
        float4 q0 = __ldg((const float4*)(bt + aa * 16) + 0);
        float4 q1 = __ldg((const float4*)(bt + aa * 16) + 1);
        float4 q2 = __ldg((const float4*)(bt + aa * 16) + 2);
        float4 q3 = __ldg((const float4*)(bt + aa * 16) + 3);
        float vv[16] = {q0.x,q0.y,q0.z,q0.w, q1.x,q1.y,q1.z,q1.w,
                        q2.x,q2.y,q2.z,q2.w, q3.x,q3.y,q3.z,q3.w};
        #pragma unroll 4
        for (int t4 = 0; t4 < 16; t4++) {
            float4 xv = *(float4*)(sTe + m * 64 + ((t4 + m) & 15) * 4);
            float xs[4] = {xv.x, xv.y, xv.z, xv.w};
            #pragma unroll
            for (int e = 0; e < 4; e++) {
                float x = xs[e];
                const float4* ur = (const float4*)(sUt + aa * 1024 + (t4 * 4 + e) * 16);
                float4 u0 = ur[0], u1 = ur[1], u2 = ur[2], u3 = ur[3];
                vv[0]+=x*u0.x; vv[1]+=x*u0.y; vv[2]+=x*u0.z; vv[3]+=x*u0.w;
                vv[4]+=x*u1.x; vv[5]+=x*u1.y; vv[6]+=x*u1.z; vv[7]+=x*u1.w;
                vv[8]+=x*u2.x; vv[9]+=x*u2.y; vv[10]+=x*u2.z; vv[11]+=x*u2.w;
                vv[12]+=x*u3.x; vv[13]+=x*u3.y; vv[14]+=x*u3.z; vv[15]+=x*u3.w;
            }
        }
        #pragma unroll
        for (int j = 0; j < 16; j++) sV[m * SV_P + aa * 16 + j] = vv[j];
        __syncthreads();
    }

    // ======== pipeline: 128 chunks = g(32) x npass(2) x kc(2), KC=128, N=128 ========
    auto issue = [&](int q) {
        const int g = q >> 2, npass = (q >> 1) & 1, kc = q & 1, buf = q & 1;
        const int c = g >> 2;
        const uint32_t aDst = sbase + OFF_SA + buf * 32768;
        #pragma unroll
        for (int s = 0; s < 4; s++) {
            int u = tid + s * 512;              // 2048: mtL(8) x ktL(8) x l(32)
            int mtL = u >> 8, ktL = (u >> 5) & 7, ll = u & 31;
            size_t o = ((size_t)(c * 1024 + mt0 + mtL) * 16 + kc * 8 + ktL) * 32 + ll;
            cpa16(aDst + u * 16, g_Af + o);
        }
        const uint32_t bDst = sbase + OFF_SB + buf * 32768;
        #pragma unroll
        for (int s = 0; s < 4; s++) {
            int v = tid + s * 512;              // 2048 16B units: ktL(8) x 256B-block rows
            int ktL = v >> 8, rem = v & 255;
            const char* src = (const char*)g_Bf
                + ((size_t)((g * 16 + kc * 8 + ktL) * 32 + npass * 16) * 32) * 8
                + (size_t)rem * 16;
            cpa16(bDst + v * 16, src);
        }
        CP_COMMIT();
    };

    float nvp[4] = {0.f, 0.f, 0.f, 0.f};
    auto reduce_half = [&](int aP, int doStore) {
        int row = tid & 127, jq = tid >> 7;
        #pragma unroll
        for (int e = 0; e < 4; e++) {
            float s = red[(0 * 128 + row) * RED_P + jq * 4 + e]
                    + red[(1 * 128 + row) * RED_P + jq * 4 + e]
                    + red[(2 * 128 + row) * RED_P + jq * 4 + e]
                    + red[(3 * 128 + row) * RED_P + jq * 4 + e];
            nvp[e] += s;
            if (doStore) {
                sV[row * SV_P + aP * 16 + jq * 4 + e] = nvp[e];
                nvp[e] = 0.f;
            }
        }
    };

    issue(0);

    float acc[2][4][4];   // mt x nt x frag (32 regs)

    #pragma unroll 1
    for (int q = 0; q < 128; q++) {
        const int g = q >> 2, kc = q & 1, buf = q & 1;
        const int npass = (q >> 1) & 1;
        const int a = g & 3;

        CP_WAIT0();
        __syncthreads();
        if (q + 1 < 128) issue(q + 1);

        // deferred reductions — each read is >=1 barrier after the red write,
        // and >=1 barrier before the next red overwrite
        if ((q & 3) == 2)            reduce_half(0, 0);          // npass0 partials of g
        else if ((q & 3) == 0 && q)  reduce_half((g - 1) & 3, 1); // npass1 of g-1, store

        if ((q & 3) == 0 && tid < 64)
            ((float4*)sBias)[tid] = __ldg((const float4*)(bB + (size_t)g * 272) + tid);
        if (kc == 0) {
            #pragma unroll
            for (int mt = 0; mt < 2; mt++)
                #pragma unroll
                for (int nt = 0; nt < 4; nt++)
                    #pragma unroll
                    for (int e = 0; e < 4; e++) acc[mt][nt][e] = 0.f;
        }

        // ---- compute: 8 k16-steps ----
        const char* sAb = smem + OFF_SA + buf * 32768;
        const char* sBb = smem + OFF_SB + buf * 32768;
        #pragma unroll
        for (int ktL = 0; ktL < 8; ktL++) {
            uint32_t Ah[2][4];
            #pragma unroll
            for (int mt = 0; mt < 2; mt++)
                *(uint4*)Ah[mt] = *(const uint4*)(sAb +
                    (((mw * 2 + mt) * 8 + ktL) * 32 + l) * 16);
            uint2 Bq[4];
            #pragma unroll
            for (int nt = 0; nt < 4; nt++)
                Bq[nt] = *(const uint2*)(sBb + ((ktL * 16 + nwp * 4 + nt) * 32 + l) * 8);
            #pragma unroll
            for (int nt = 0; nt < 4; nt++)
                #pragma unroll
                for (int mt = 0; mt < 2; mt++)
                    mma_f16(acc[mt][nt], Ah[mt], Bq[nt].x, Bq[nt].y);
        }

        // ---- epilogue: scan partials for (g, npass) ----
        if (kc == 1) {
            const int i0 = npass * 8 + nwp * 2, i1 = i0 + 1;
            const int j0 = (l & 3) * 2;
            float2 b00 = *(float2*)(sBias + i0 * 16 + j0);
            float2 b01 = *(float2*)(sBias + i1 * 16 + j0);
            float2 b10 = *(float2*)(sBias + i0 * 16 + j0 + 8);
            float2 b11 = *(float2*)(sBias + i1 * 16 + j0 + 8);
            const float add1 = (i1 == 15) ? 1.f : 0.f;
            const int rbase = mw * 32 + (l >> 2);
            #pragma unroll
            for (int p = 0; p < 4; p++) {
                int row = rbase + p * 8;
                int mt = p >> 1, h = (p & 1) * 2;
                float c0 = sV[row * SV_P + a * 16 + i0];
                float c1 = sV[row * SV_P + a * 16 + i1] + add1;
                float2 pj, pk;
                pj.x = c0 * (acc[mt][0][h+0] + b00.x) + c1 * (acc[mt][2][h+0] + b01.x);
                pj.y = c0 * (acc[mt][0][h+1] + b00.y) + c1 * (acc[mt][2][h+1] + b01.y);
                pk.x = c0 * (acc[mt][1][h+0] + b10.x) + c1 * (acc[mt][3][h+0] + b11.x);
                pk.y = c0 * (acc[mt][1][h+1] + b10.y) + c1 * (acc[mt][3][h+1] + b11.y);
                *(float2*)(red + (nwp * 128 + row) * RED_P + j0)     = pj;
                *(float2*)(red + (nwp * 128 + row) * RED_P + j0 + 8) = pk;
            }
        }
    }

    __syncthreads();                // g=31 npass1 partials visible
    reduce_half(3, 1);
    __syncthreads();

    // ================= output projection (single pass, a = tid>>7 in 0..3) ============
    {
        float* sUo = (float*)(smem + OFF_SA);           // 16384 floats spans both A bufs
        float* sBo = (float*)(smem + OFF_SB);           // 1024 floats
        #pragma unroll
        for (int i = 0; i < 8; i++) {
            int idx = tid + i * 512;
            ((float4*)sUo)[idx] = __ldg((const float4*)Uo + idx);
        }
        if (tid < 256) ((float4*)sBo)[tid] = __ldg((const float4*)bo + tid);
        __syncthreads();
        const int a = tid >> 7, h2 = (tid & 127) * 2;
        float2 uo[16];
        #pragma unroll
        for (int r = 0; r < 16; r++)
            uo[r] = *(float2*)(sUo + (a * 16 + r) * 256 + h2);
        float2 b2 = *(float2*)(sBo + a * 256 + h2);
        #pragma unroll 2
        for (int m = 0; m < 128; m++) {
            float sx = b2.x, sy = b2.y;
            const float* vr = sV + m * SV_P + a * 16;
            #pragma unroll
            for (int r = 0; r < 16; r++) {
                float vvv = vr[r];
                sx += vvv * uo[r].x; sy += vvv * uo[r].y;
            }
            *(float2*)(out + (size_t)(b0 + m) * 1024 + a * 256 + h2) = make_float2(sx, sy);
        }
    }
}

extern "C" void kernel_launch(void* const* d_in, const int* in_sizes, int n_in,
                              void* d_out, int out_size) {
    const float* nh = (const float*)d_in[0];
    const float* te = (const float*)d_in[1];
    const float* U  = (const float*)d_in[2];
    const float* bB = (const float*)d_in[3];
    const float* Ut = (const float*)d_in[4];
    const float* bt = (const float*)d_in[5];
    const float* Uo = (const float*)d_in[6];
    const float* bo = (const float*)d_in[7];
    float* out = (float*)d_out;

    prep_A<<<8192, 256>>>(nh);
    prep_B<<<512, 256>>>(U);
    cudaFuncSetAttribute(tt_main, cudaFuncAttributeMaxDynamicSharedMemorySize, SMEM_SZ);
    tt_main<<<128, 512, SMEM_SZ>>>(te, bB, Ut, bt, Uo, bo, out);
}

// round 12
// speedup vs baseline: 3.1566x; 1.1252x over previous
#include <cuda_runtime.h>
#include <cuda_fp16.h>
#include <cstdint>

#define NG 32
#define SV_P 65
#define RED_P 18

// A fragments fp16: [c(8)][mt(1024)][kt(16)][lane(32)] uint4 {a0,a1,a2,a3}
__device__ uint4 g_Af[8 * 1024 * 16 * 32];
// B fragments fp16, n8-tile PAIRS: [g(32)][kt(16)][ntp(16)][lane(32)] uint4
//   {b0(ntA), b1(ntA), b0(ntB), b1(ntB)}  with ntA=2*ntp, ntB=2*ntp+1
__device__ uint4 g_Bf[NG * 16 * 16 * 32];

// ---- smem map (bytes) ----
#define OFF_BIAS 0          // 1024
#define OFF_SV   1024       // 128*65*4 = 33280
#define OFF_RED  34304      // 4*128*18*4 = 36864 (also v0's sTe scratch)
#define OFF_SA   71168      // 2 x 16384
#define OFF_SB   103936     // 2 x 32768
#define SMEM_SZ  169472

__device__ __forceinline__ uint32_t s2u(const void* p) {
    uint32_t a;
    asm("{ .reg .u64 t; cvta.to.shared.u64 t, %1; cvt.u32.u64 %0, t; }" : "=r"(a) : "l"(p));
    return a;
}
__device__ __forceinline__ uint32_t pack_h2(float x, float y) {
    __half2 h = __floats2half2_rn(x, y);
    return *(uint32_t*)&h;
}
__device__ __forceinline__ void mma_f16(float* c, const uint32_t* a, uint32_t b0, uint32_t b1) {
    asm volatile(
        "mma.sync.aligned.m16n8k16.row.col.f32.f16.f16.f32 "
        "{%0,%1,%2,%3}, {%4,%5,%6,%7}, {%8,%9}, {%0,%1,%2,%3};"
        : "+f"(c[0]), "+f"(c[1]), "+f"(c[2]), "+f"(c[3])
        : "r"(a[0]), "r"(a[1]), "r"(a[2]), "r"(a[3]), "r"(b0), "r"(b1));
}
__device__ __forceinline__ void cpa16(uint32_t dst, const void* src) {
    asm volatile("cp.async.cg.shared.global [%0], [%1], 16;" :: "r"(dst), "l"(src) : "memory");
}
#define CP_COMMIT() asm volatile("cp.async.commit_group;" ::: "memory")
#define CP_WAIT0()  asm volatile("cp.async.wait_group 0;" ::: "memory")

// ---------------- prep_A: nh f32 -> fp16 A fragments ----------------
__global__ __launch_bounds__(256) void prep_A(const float* __restrict__ nh) {
    const int blk = blockIdx.x;              // 8192 = c(8) x mt(1024)
    const int c = blk >> 10, mt = blk & 1023;
    #pragma unroll
    for (int s = 0; s < 2; s++) {
        int u = threadIdx.x + s * 256;       // kt(16) x lane(32)
        int kt = u >> 5, l = u & 31;
        int row = mt * 16 + (l >> 2);
        int k = kt * 16 + (l & 3) * 2;
        const float* p = nh + ((size_t)row * 8 + c) * 256 + k;
        float2 x0 = __ldg((const float2*)p);                   // (r,   k)
        float2 x1 = __ldg((const float2*)(p + 8 * 2048));      // (r+8, k)
        float2 x2 = __ldg((const float2*)(p + 8));             // (r,   k+8)
        float2 x3 = __ldg((const float2*)(p + 8 * 2048 + 8));  // (r+8, k+8)
        size_t o = ((size_t)(c * 1024 + mt) * 16 + kt) * 32 + l;
        g_Af[o] = make_uint4(pack_h2(x0.x, x0.y), pack_h2(x1.x, x1.y),
                             pack_h2(x2.x, x2.y), pack_h2(x3.x, x3.y));
    }
}

// ---------------- prep_B: U f32 -> fp16 B fragment pairs ----------------
__global__ __launch_bounds__(256) void prep_B(const float* __restrict__ U) {
    const int blk = blockIdx.x;              // 512 = g(32) x kt(16)
    const int g = blk >> 4, kt = blk & 15;
    const float* Ug = U + (size_t)g * 256 * 272;
    #pragma unroll
    for (int s = 0; s < 2; s++) {
        int u = threadIdx.x + s * 256;       // ntp(16) x lane(32)
        int ntp = u >> 5, l = u & 31;
        int k0 = kt * 16 + (l & 3) * 2;
        int nA = ntp * 16 + (l >> 2), nB = nA + 8;
        float a0 = __ldg(Ug + (size_t)k0 * 272 + nA);
        float a1 = __ldg(Ug + (size_t)(k0 + 1) * 272 + nA);
        float a8 = __ldg(Ug + (size_t)(k0 + 8) * 272 + nA);
        float a9 = __ldg(Ug + (size_t)(k0 + 9) * 272 + nA);
        float c0 = __ldg(Ug + (size_t)k0 * 272 + nB);
        float c1 = __ldg(Ug + (size_t)(k0 + 1) * 272 + nB);
        float c8 = __ldg(Ug + (size_t)(k0 + 8) * 272 + nB);
        float c9 = __ldg(Ug + (size_t)(k0 + 9) * 272 + nB);
        g_Bf[((size_t)(g * 16 + kt) * 16 + ntp) * 32 + l] =
            make_uint4(pack_h2(a0, a1), pack_h2(a8, a9),
                       pack_h2(c0, c1), pack_h2(c8, c9));
    }
}

// ---- main: 128 CTAs x 512 threads (16 warps: mw4 x nwp4, warp tile 32x64), KC=64, N=256
__global__ __launch_bounds__(512, 1)
void tt_main(const float* __restrict__ te, const float* __restrict__ bB,
             const float* __restrict__ Ut, const float* __restrict__ bt,
             const float* __restrict__ Uo, const float* __restrict__ bo,
             float* __restrict__ out)
{
    extern __shared__ __align__(16) char smem[];
    const uint32_t sbase = s2u(smem);
    float* sBias = (float*)(smem + OFF_BIAS);
    float* sV    = (float*)(smem + OFF_SV);
    float* red   = (float*)(smem + OFF_RED);

    const int tid = threadIdx.x;
    const int l   = tid & 31, w = tid >> 5;
    const int mw  = w >> 2,  nwp = w & 3;       // warp grid 4M x 4N (tile 32x64)
    const int b0  = blockIdx.x * 128;
    const int mt0 = blockIdx.x * 8;

    // ================= v0 = te @ U_type + b_type =================
    {
        float* sUt = (float*)(smem + OFF_SA);   // 4096 floats
        float* sTe = red;                       // 128x64, float4-rotated (32 KB)
        #pragma unroll
        for (int i = 0; i < 2; i++) {
            int idx = tid + i * 512;
            ((float4*)sUt)[idx] = __ldg((const float4*)Ut + idx);
        }
        #pragma unroll
        for (int i = 0; i < 4; i++) {
            int u = tid + i * 512;              // 2048 float4 units
            int m = u >> 4, t4 = u & 15;
            *(float4*)(sTe + m * 64 + ((t4 + m) & 15) * 4) =
                __ldg((const float4*)(te + (size_t)(b0 + m) * 64) + t4);
        }
        __syncthreads();
        const int m = tid & 127, aa = tid >> 7;
        float4 q0 = __ldg((const float4*)(bt + aa * 16) + 0);
        float4 q1 = __ldg((const float4*)(bt + aa * 16) + 1);
        float4 q2 = __ldg((const float4*)(bt + aa * 16) + 2);
        float4 q3 = __ldg((const float4*)(bt + aa * 16) + 3);
        float vv[16] = {q0.x,q0.y,q0.z,q0.w, q1.x,q1.y,q1.z,q1.w,
                        q2.x,q2.y,q2.z,q2.w, q3.x,q3.y,q3.z,q3.w};
        #pragma unroll 4
        for (int t4 = 0; t4 < 16; t4++) {
            float4 xv = *(float4*)(sTe + m * 64 + ((t4 + m) & 15) * 4);
            float xs[4] = {xv.x, xv.y, xv.z, xv.w};
            #pragma unroll
            for (int e = 0; e < 4; e++) {
                float x = xs[e];
                const float4* ur = (const float4*)(sUt + aa * 1024 + (t4 * 4 + e) * 16);
                float4 u0 = ur[0], u1 = ur[1], u2 = ur[2], u3 = ur[3];
                vv[0]+=x*u0.x; vv[1]+=x*u0.y; vv[2]+=x*u0.z; vv[3]+=x*u0.w;
                vv[4]+=x*u1.x; vv[5]+=x*u1.y; vv[6]+=x*u1.z; vv[7]+=x*u1.w;
                vv[8]+=x*u2.x; vv[9]+=x*u2.y; vv[10]+=x*u2.z; vv[11]+=x*u2.w;
                vv[12]+=x*u3.x; vv[13]+=x*u3.y; vv[14]+=x*u3.z; vv[15]+=x*u3.w;
            }
        }
        #pragma unroll
        for (int j = 0; j < 16; j++) sV[m * SV_P + aa * 16 + j] = vv[j];
        __syncthreads();
    }

    // ================= pipeline: 128 chunks = g(32) x kc(4), KC=64, N=256 =============
    auto issue = [&](int q) {
        const int g = q >> 2, kc = q & 3, buf = q & 1;
        const int c = g >> 2;
        const uint32_t aDst = sbase + OFF_SA + buf * 16384;
        #pragma unroll
        for (int s = 0; s < 2; s++) {
            int u = tid + s * 512;              // 1024: mtL(8) x ktL(4) x l(32)
            int mtL = u >> 7, ktL = (u >> 5) & 3, ll = u & 31;
            size_t o = ((size_t)(c * 1024 + mt0 + mtL) * 16 + kc * 4 + ktL) * 32 + ll;
            cpa16(aDst + u * 16, g_Af + o);
        }
        const uint32_t bDst = sbase + OFF_SB + buf * 32768;
        #pragma unroll
        for (int s = 0; s < 4; s++) {
            int u = tid + s * 512;              // 2048: ktL(4) x ntp(16) x l(32)
            int ktL = u >> 9, ntp = (u >> 5) & 15, ll = u & 31;
            size_t o = ((size_t)(g * 16 + kc * 4 + ktL) * 16 + ntp) * 32 + ll;
            cpa16(bDst + u * 16, g_Bf + o);
        }
        CP_COMMIT();
    };

    auto reduce_g = [&](int aP) {   // single-shot: 4 warps' partials cover all 16 i
        int row = tid & 127, jq = tid >> 7;
        #pragma unroll
        for (int e = 0; e < 4; e++) {
            float s = red[(0 * 128 + row) * RED_P + jq * 4 + e]
                    + red[(1 * 128 + row) * RED_P + jq * 4 + e]
                    + red[(2 * 128 + row) * RED_P + jq * 4 + e]
                    + red[(3 * 128 + row) * RED_P + jq * 4 + e];
            sV[row * SV_P + aP * 16 + jq * 4 + e] = s;
        }
    };

    issue(0);

    float acc[2][8][4];   // mt x nt(8 n8-tiles) x frag  (64 regs)

    #pragma unroll 1
    for (int q = 0; q < 128; q++) {
        const int g = q >> 2, kc = q & 3, buf = q & 1;
        const int a = g & 3;

        CP_WAIT0();
        __syncthreads();
        if (q + 1 < 128) issue(q + 1);

        if (kc == 1 && q >= 4) reduce_g((g - 1) & 3);

        if (kc == 0) {
            if (tid < 64)
                ((float4*)sBias)[tid] = __ldg((const float4*)(bB + (size_t)g * 272) + tid);
            #pragma unroll
            for (int mt = 0; mt < 2; mt++)
                #pragma unroll
                for (int nt = 0; nt < 8; nt++)
                    #pragma unroll
                    for (int e = 0; e < 4; e++) acc[mt][nt][e] = 0.f;
        }

        // ---- compute: 4 k16-steps x 8 n8-tiles ----
        const char* sAb = smem + OFF_SA + buf * 16384;
        const char* sBb = smem + OFF_SB + buf * 32768;
        #pragma unroll
        for (int ktL = 0; ktL < 4; ktL++) {
            uint32_t Ah[2][4];
            #pragma unroll
            for (int mt = 0; mt < 2; mt++)
                *(uint4*)Ah[mt] = *(const uint4*)(sAb +
                    (((mw * 2 + mt) * 4 + ktL) * 32 + l) * 16);
            uint4 Bp[4];
            #pragma unroll
            for (int np = 0; np < 4; np++)
                Bp[np] = *(const uint4*)(sBb +
                    ((ktL * 16 + nwp * 4 + np) * 32 + l) * 16);
            #pragma unroll
            for (int np = 0; np < 4; np++)
                #pragma unroll
                for (int mt = 0; mt < 2; mt++) {
                    mma_f16(acc[mt][np * 2],     Ah[mt], Bp[np].x, Bp[np].y);
                    mma_f16(acc[mt][np * 2 + 1], Ah[mt], Bp[np].z, Bp[np].w);
                }
        }

        // ---- epilogue: warp owns i = nwp*4..+4, all 16 i covered per g ----
        if (kc == 3) {
            const int j0 = (l & 3) * 2;
            #pragma unroll
            for (int p = 0; p < 4; p++) {
                int row = mw * 32 + (l >> 2) + p * 8;
                int mt = p >> 1, h = (p & 1) * 2;
                float2 pj = make_float2(0.f, 0.f), pk = make_float2(0.f, 0.f);
                #pragma unroll
                for (int np = 0; np < 4; np++) {
                    int i = nwp * 4 + np;
                    float coef = sV[row * SV_P + a * 16 + i] + ((i == 15) ? 1.f : 0.f);
                    float2 bj = *(float2*)(sBias + i * 16 + j0);
                    float2 bk = *(float2*)(sBias + i * 16 + j0 + 8);
                    pj.x += coef * (acc[mt][np * 2][h + 0] + bj.x);
                    pj.y += coef * (acc[mt][np * 2][h + 1] + bj.y);
                    pk.x += coef * (acc[mt][np * 2 + 1][h + 0] + bk.x);
                    pk.y += coef * (acc[mt][np * 2 + 1][h + 1] + bk.y);
                }
                *(float2*)(red + (nwp * 128 + row) * RED_P + j0)     = pj;
                *(float2*)(red + (nwp * 128 + row) * RED_P + j0 + 8) = pk;
            }
        }
    }

    __syncthreads();                // g=31 partials visible
    reduce_g(3);
    __syncthreads();

    // ================= output projection (single pass, a = tid>>7 in 0..3) ============
    {
        float* sUo = (float*)(smem + OFF_SA);           // 64 KB overlay (SA + SB head)
        float* sBo = (float*)(smem + OFF_SA + 65536);   // 1024 floats
        #pragma unroll
        for (int i = 0; i < 8; i++) {
            int idx = tid + i * 512;
            ((float4*)sUo)[idx] = __ldg((const float4*)Uo + idx);
        }
        if (tid < 256) ((float4*)sBo)[tid] = __ldg((const float4*)bo + tid);
        __syncthreads();
        const int a = tid >> 7, h2 = (tid & 127) * 2;
        float2 uo[16];
        #pragma unroll
        for (int r = 0; r < 16; r++)
            uo[r] = *(float2*)(sUo + (a * 16 + r) * 256 + h2);
        float2 b2 = *(float2*)(sBo + a * 256 + h2);
        #pragma unroll 2
        for (int m = 0; m < 128; m++) {
            float sx = b2.x, sy = b2.y;
            const float* vr = sV + m * SV_P + a * 16;
            #pragma unroll
            for (int r = 0; r < 16; r++) {
                float vvv = vr[r];
                sx += vvv * uo[r].x; sy += vvv * uo[r].y;
            }
            *(float2*)(out + (size_t)(b0 + m) * 1024 + a * 256 + h2) = make_float2(sx, sy);
        }
    }
}

extern "C" void kernel_launch(void* const* d_in, const int* in_sizes, int n_in,
                              void* d_out, int out_size) {
    const float* nh = (const float*)d_in[0];
    const float* te = (const float*)d_in[1];
    const float* U  = (const float*)d_in[2];
    const float* bB = (const float*)d_in[3];
    const float* Ut = (const float*)d_in[4];
    const float* bt = (const float*)d_in[5];
    const float* Uo = (const float*)d_in[6];
    const float* bo = (const float*)d_in[7];
    float* out = (float*)d_out;

    prep_A<<<8192, 256>>>(nh);
    prep_B<<<512, 256>>>(U);
    cudaFuncSetAttribute(tt_main, cudaFuncAttributeMaxDynamicSharedMemorySize, SMEM_SZ);
    tt_main<<<128, 512, SMEM_SZ>>>(te, bB, Ut, bt, Uo, bo, out);
}